// round 17
// baseline (speedup 1.0000x reference)
#include <cuda_runtime.h>
#include <cuda_bf16.h>
#include <cstdint>

// ---------------------------------------------------------------------------
// LastAggregator: out[n, :] = msg[argmax_{i : index[i]==n} t[i], :]
// (ties -> smallest i; empty segments -> zeros)
//
//   key(i) = (total_order(t[i]) << 32) | ~i    packed into u64
//   atomicMax over keys per segment  ->  winner = ~(low 32 bits)
//   key == 0  <=>  empty segment (valid keys have nonzero low word).
//
// Two-kernel structure with Programmatic Dependent Launch: the gather is
// launched with programmaticStreamSerializationAllowed=1 so its blocks are
// pre-launched during argmax; cudaGridDependencySynchronize() gates the key
// reads on argmax completion (implicit trigger -> all atomics visible).
//
// Self-cleaning: gather resets consumed keys to 0 -- device-global zero-init
// covers call 1, every call leaves state clean.
//
// index arrives as int32 (JAX x64 disabled downcasts the declared int64).
// ---------------------------------------------------------------------------

#define MAX_SEGMENTS (1 << 17)  // 131072 >= N = 65536
__device__ unsigned long long g_key[MAX_SEGMENTS];

__device__ __forceinline__ void stcs_f4(float4* p, float4 v) {
    // streaming store: write-once output, evict-first so it never displaces
    // winner rows from L2
    asm volatile("st.global.cs.v4.f32 [%0], {%1,%2,%3,%4};"
                 :: "l"(p), "f"(v.x), "f"(v.y), "f"(v.z), "f"(v.w) : "memory");
}

__device__ __forceinline__ unsigned long long
make_key(float tv, unsigned int i) {
    unsigned int fb  = __float_as_uint(tv);
    unsigned int ord = (fb & 0x80000000u) ? ~fb : (fb | 0x80000000u);
    return ((unsigned long long)ord << 32) | (unsigned long long)(~i);
}

// --- argmax: 4 events per thread, vectorized loads --------------------------
__global__ void la_argmax_kernel(const int* __restrict__ index,
                                 const float* __restrict__ t,
                                 int M, int N) {
    int base = (blockIdx.x * blockDim.x + threadIdx.x) * 4;
    if (base + 3 < M) {
        int4   s  = *reinterpret_cast<const int4*>(index + base);
        float4 tv = *reinterpret_cast<const float4*>(t + base);
        int   segs[4] = {s.x, s.y, s.z, s.w};
        float ts[4]   = {tv.x, tv.y, tv.z, tv.w};
#pragma unroll
        for (int k = 0; k < 4; ++k) {
            unsigned long long key = make_key(ts[k], (unsigned int)(base + k));
            int seg = segs[k];
            if (seg >= 0 && seg < N) atomicMax(&g_key[seg], key);  // -> REDG
        }
    } else {
        for (int i = base; i < M; ++i) {
            unsigned long long key = make_key(t[i], (unsigned int)i);
            int seg = index[i];
            if (seg >= 0 && seg < N) atomicMax(&g_key[seg], key);
        }
    }
}

// --- D=256 gather: one warp per 2 rows; PDL-gated; self-cleans keys ---------
// Each thread: 4 independent LDG.128 chains + 4 STG.128. Keys are loaded by
// all lanes at a uniform address (L1 broadcast).
__global__ void la_gather_d256_kernel(const float4* __restrict__ msg,
                                      float4* __restrict__ out,
                                      int N) {
    // preamble (runs while argmax may still be executing)
    int gwarp = (blockIdx.x * blockDim.x + threadIdx.x) >> 5;
    int lane  = threadIdx.x & 31;
    int r0 = gwarp * 2;
    int r1 = r0 + 1;
    bool has1 = (r1 < N);
    size_t ob0 = (size_t)r0 * 64;
    size_t ob1 = (size_t)r1 * 64;

    // gate: wait for argmax grid completion (atomics then globally visible)
    cudaGridDependencySynchronize();

    if (r0 >= N) return;

    unsigned long long key0 = g_key[r0];
    unsigned long long key1 = has1 ? g_key[r1] : 0ull;
    if (lane == 0) {                        // self-clean for next call
        g_key[r0] = 0ull;
        if (has1) g_key[r1] = 0ull;
    }

    const float4 z = make_float4(0.f, 0.f, 0.f, 0.f);
    float4 a0 = z, a1 = z, b0 = z, b1 = z;
    if (key0 != 0ull) {
        size_t ib = (size_t)(~(unsigned int)(key0 & 0xFFFFFFFFull)) * 64;
        a0 = __ldg(&msg[ib + lane]);
        a1 = __ldg(&msg[ib + lane + 32]);
    }
    if (has1 && key1 != 0ull) {
        size_t ib = (size_t)(~(unsigned int)(key1 & 0xFFFFFFFFull)) * 64;
        b0 = __ldg(&msg[ib + lane]);
        b1 = __ldg(&msg[ib + lane + 32]);
    }
    stcs_f4(&out[ob0 + lane],      a0);
    stcs_f4(&out[ob0 + lane + 32], a1);
    if (has1) {
        stcs_f4(&out[ob1 + lane],      b0);
        stcs_f4(&out[ob1 + lane + 32], b1);
    }
}

// --- generic fallback (unexpected D): init + argmax + gather ----------------
__global__ void la_init_kernel(int N) {
    int i = blockIdx.x * blockDim.x + threadIdx.x;
    if (i < N) g_key[i] = 0ull;
}

__global__ void la_gather_generic_kernel(const float4* __restrict__ msg,
                                         float4* __restrict__ out,
                                         int N, int D4) {
    long long e = (long long)blockIdx.x * blockDim.x + threadIdx.x;
    long long total = (long long)N * D4;
    if (e >= total) return;
    int row  = (int)(e / D4);
    int lane = (int)(e % D4);
    unsigned long long key = g_key[row];
    float4 v = make_float4(0.f, 0.f, 0.f, 0.f);
    if (key != 0ull) {
        unsigned int win = ~(unsigned int)(key & 0xFFFFFFFFull);
        v = __ldg(&msg[(size_t)win * D4 + lane]);
    }
    out[(size_t)row * D4 + lane] = v;
}

extern "C" void kernel_launch(void* const* d_in, const int* in_sizes, int n_in,
                              void* d_out, int out_size) {
    // metadata order: msg [M*D f32], index [M i32], t [M f32], (dim_size)
    const float* msg   = (const float*)d_in[0];
    const int*   index = (const int*)d_in[1];
    const float* t     = (const float*)d_in[2];
    float*       out   = (float*)d_out;

    int M = in_sizes[1];              // 262144
    int D = in_sizes[0] / M;          // 256
    int N = out_size / D;             // 65536
    if (N > MAX_SEGMENTS) N = MAX_SEGMENTS;

    if (D == 256) {
        {   // argmax: 4 events/thread
            int threads = 256;
            int per_blk = threads * 4;
            int blocks  = (M + per_blk - 1) / per_blk;
            la_argmax_kernel<<<blocks, threads>>>(index, t, M, N);
        }
        {   // gather: PDL so its blocks prelaunch during argmax
            int threads = 256;                     // 8 warps = 16 rows/block
            int rows_per_blk = (threads / 32) * 2;
            int blocks = (N + rows_per_blk - 1) / rows_per_blk;

            cudaLaunchConfig_t cfg = {};
            cfg.gridDim  = dim3((unsigned)blocks, 1, 1);
            cfg.blockDim = dim3((unsigned)threads, 1, 1);
            cfg.dynamicSmemBytes = 0;
            cfg.stream = 0;  // legacy default stream (same as <<<>>>)
            cudaLaunchAttribute attrs[1];
            attrs[0].id = cudaLaunchAttributeProgrammaticStreamSerialization;
            attrs[0].val.programmaticStreamSerializationAllowed = 1;
            cfg.attrs = attrs;
            cfg.numAttrs = 1;
            cudaLaunchKernelEx(&cfg, la_gather_d256_kernel,
                               (const float4*)msg, (float4*)out, N);
        }
    } else {
        // generic safe path
        {
            int threads = 256;
            int blocks  = (N + threads - 1) / threads;
            la_init_kernel<<<blocks, threads>>>(N);
        }
        {
            int threads = 256;
            int per_blk = threads * 4;
            int blocks  = (M + per_blk - 1) / per_blk;
            la_argmax_kernel<<<blocks, threads>>>(index, t, M, N);
        }
        {
            int D4 = D / 4;
            long long total = (long long)N * D4;
            int threads = 256;
            int blocks  = (int)((total + threads - 1) / threads);
            la_gather_generic_kernel<<<blocks, threads>>>((const float4*)msg,
                                                          (float4*)out, N, D4);
        }
    }
}